// round 2
// baseline (speedup 1.0000x reference)
#include <cuda_runtime.h>
#include <cuda_bf16.h>
#include <math.h>

// Problem constants (match reference)
#define NBX     512
#define NBY     512
#define BSX     1.953125f   // 1000/512, exact in fp32
#define BSY     1.953125f
#define INV_UPC 10.0f       // 1 / UNIT_PIN_CAP

// Each thread processes 4 consecutive nodes with vectorized streaming access.
__global__ __launch_bounds__(256) void node_area_kernel_v4(
    const float* __restrict__ pos,        // [2N]: x then y
    const float* __restrict__ nsx,        // [N]
    const float* __restrict__ nsy,        // [N]
    const float* __restrict__ umap,       // [NBX*NBY], row-major [bx][by]
    const int*   __restrict__ pw,         // [N]
    float*       __restrict__ out,        // [N]
    int n)
{
    int base = (blockIdx.x * blockDim.x + threadIdx.x) * 4;
    if (base >= n) return;
    // n is a multiple of 4 (N=2,000,000), so a full float4 is always valid.

    float4 x4 = *(const float4*)(pos + base);
    float4 y4 = *(const float4*)(pos + n + base);
    float4 w4 = *(const float4*)(nsx + base);
    float4 h4 = *(const float4*)(nsy + base);
    int4   p4 = *(const int4*)(pw + base);

    float xs[4] = {x4.x, x4.y, x4.z, x4.w};
    float ys[4] = {y4.x, y4.y, y4.z, y4.w};
    float ws[4] = {w4.x, w4.y, w4.z, w4.w};
    float hs[4] = {h4.x, h4.y, h4.z, h4.w};
    int   ps[4] = {p4.x, p4.y, p4.z, p4.w};

    float u00[4], u01[4], u10[4], u11[4];
    float ox0[4], ox1[4], oy0[4], oy1[4];

    // Phase 1: bin math + issue all 16 gathers (independent -> deep MLP)
    #pragma unroll
    for (int k = 0; k < 4; k++) {
        float x = xs[k], y = ys[k];
        float hix = x + ws[k];
        float hiy = y + hs[k];

        int bx0 = (int)floorf(x / BSX);
        int by0 = (int)floorf(y / BSY);

        float blx0 = (float)bx0 * BSX;
        ox0[k] = fmaxf(fminf(hix, blx0 + BSX)        - fmaxf(x, blx0),       0.0f);
        ox1[k] = fmaxf(fminf(hix, blx0 + 2.0f * BSX) - fmaxf(x, blx0 + BSX), 0.0f);

        float bly0 = (float)by0 * BSY;
        oy0[k] = fmaxf(fminf(hiy, bly0 + BSY)        - fmaxf(y, bly0),       0.0f);
        oy1[k] = fmaxf(fminf(hiy, bly0 + 2.0f * BSY) - fmaxf(y, bly0 + BSY), 0.0f);

        int bx0c = min(max(bx0,     0), NBX - 1);
        int bx1c = min(max(bx0 + 1, 0), NBX - 1);
        int by0c = min(max(by0,     0), NBY - 1);
        int by1c = min(max(by0 + 1, 0), NBY - 1);

        const float* row0 = umap + bx0c * NBY;
        const float* row1 = umap + bx1c * NBY;
        u00[k] = __ldg(&row0[by0c]);
        u01[k] = __ldg(&row0[by1c]);
        u10[k] = __ldg(&row1[by0c]);
        u11[k] = __ldg(&row1[by1c]);
    }

    // Phase 2: reduce + store
    float4 r;
    float res[4];
    #pragma unroll
    for (int k = 0; k < 4; k++) {
        float area = ox0[k] * (oy0[k] * u00[k] + oy1[k] * u01[k])
                   + ox1[k] * (oy0[k] * u10[k] + oy1[k] * u11[k]);
        res[k] = area * (float)ps[k] * INV_UPC / (ws[k] * hs[k]);
    }
    r.x = res[0]; r.y = res[1]; r.z = res[2]; r.w = res[3];
    *(float4*)(out + base) = r;
}

extern "C" void kernel_launch(void* const* d_in, const int* in_sizes, int n_in,
                              void* d_out, int out_size)
{
    const float* pos  = (const float*)d_in[0];
    const float* nsx  = (const float*)d_in[1];
    const float* nsy  = (const float*)d_in[2];
    const float* umap = (const float*)d_in[3];
    const int*   pw   = (const int*)d_in[4];
    float*       out  = (float*)d_out;

    int n = in_sizes[1];  // node_size_x has N elements
    int threads = 256;
    int elems_per_block = threads * 4;
    int blocks = (n + elems_per_block - 1) / elems_per_block;
    node_area_kernel_v4<<<blocks, threads>>>(pos, nsx, nsy, umap, pw, out, n);
}

// round 3
// speedup vs baseline: 1.0416x; 1.0416x over previous
#include <cuda_runtime.h>
#include <cuda_bf16.h>
#include <math.h>

// Problem constants (match reference)
#define NBX     512
#define NBY     512
#define BSX     1.953125f   // 1000/512, exact in fp32
#define BSY     1.953125f
#define INV_UPC 10.0f       // 1 / UNIT_PIN_CAP

// Select element `off` (0..3) from a float4 without local-memory spill.
__device__ __forceinline__ float sel4(float4 q, int off) {
    float r = q.x;
    r = (off == 1) ? q.y : r;
    r = (off == 2) ? q.z : r;
    r = (off == 3) ? q.w : r;
    return r;
}

// Gather u[row][j0] and u[row][j1] (j1 == j0+1 or clipped to j0) using one
// aligned float4 load, with a scalar fallback only when j1 crosses into the
// next 16B chunk (~25% of lanes).
__device__ __forceinline__ void gather_row(const float* __restrict__ row,
                                           int j0, int j1,
                                           float& u0, float& u1) {
    int a0 = j0 >> 2, o0 = j0 & 3;
    float4 q = __ldg((const float4*)row + a0);
    u0 = sel4(q, o0);
    int a1 = j1 >> 2;
    if (a1 == a0) {
        u1 = sel4(q, j1 & 3);
    } else {
        u1 = __ldg(row + j1);
    }
}

__global__ __launch_bounds__(256) void node_area_kernel_v5(
    const float* __restrict__ pos,        // [2N]: x then y
    const float* __restrict__ nsx,        // [N]
    const float* __restrict__ nsy,        // [N]
    const float* __restrict__ umap,       // [NBX*NBY], row-major [bx][by]
    const int*   __restrict__ pw,         // [N]
    float*       __restrict__ out,        // [N]
    int n)
{
    int base = (blockIdx.x * blockDim.x + threadIdx.x) * 4;
    if (base >= n) return;
    // N is a multiple of 4, so full float4 accesses are always valid.

    float4 x4 = *(const float4*)(pos + base);
    float4 y4 = *(const float4*)(pos + n + base);
    float4 w4 = *(const float4*)(nsx + base);
    float4 h4 = *(const float4*)(nsy + base);
    int4   p4 = *(const int4*)(pw + base);

    float xs[4] = {x4.x, x4.y, x4.z, x4.w};
    float ys[4] = {y4.x, y4.y, y4.z, y4.w};
    float ws[4] = {w4.x, w4.y, w4.z, w4.w};
    float hs[4] = {h4.x, h4.y, h4.z, h4.w};
    int   ps[4] = {p4.x, p4.y, p4.z, p4.w};

    float res[4];

    #pragma unroll
    for (int k = 0; k < 4; k++) {
        float x = xs[k], y = ys[k];
        float hix = x + ws[k];
        float hiy = y + hs[k];

        // floor bin indices — fp32 division matches JAX edge behavior
        int bx0 = (int)floorf(x / BSX);
        int by0 = (int)floorf(y / BSY);

        // Overlaps use UNCLIPPED bin positions (as in reference)
        float blx0 = (float)bx0 * BSX;
        float ox0 = fmaxf(fminf(hix, blx0 + BSX)        - fmaxf(x, blx0),       0.0f);
        float ox1 = fmaxf(fminf(hix, blx0 + 2.0f * BSX) - fmaxf(x, blx0 + BSX), 0.0f);

        float bly0 = (float)by0 * BSY;
        float oy0 = fmaxf(fminf(hiy, bly0 + BSY)        - fmaxf(y, bly0),       0.0f);
        float oy1 = fmaxf(fminf(hiy, bly0 + 2.0f * BSY) - fmaxf(y, bly0 + BSY), 0.0f);

        // Clipped indices for map fetch
        int bx0c = min(max(bx0,     0), NBX - 1);
        int bx1c = min(max(bx0 + 1, 0), NBX - 1);
        int by0c = min(max(by0,     0), NBY - 1);
        int by1c = min(max(by0 + 1, 0), NBY - 1);

        const float* row0 = umap + bx0c * NBY;
        const float* row1 = umap + bx1c * NBY;

        float u00, u01, u10, u11;
        gather_row(row0, by0c, by1c, u00, u01);
        gather_row(row1, by0c, by1c, u10, u11);

        float area = ox0 * (oy0 * u00 + oy1 * u01)
                   + ox1 * (oy0 * u10 + oy1 * u11);

        res[k] = area * (float)ps[k] * INV_UPC / (ws[k] * hs[k]);
    }

    float4 r;
    r.x = res[0]; r.y = res[1]; r.z = res[2]; r.w = res[3];
    *(float4*)(out + base) = r;
}

extern "C" void kernel_launch(void* const* d_in, const int* in_sizes, int n_in,
                              void* d_out, int out_size)
{
    const float* pos  = (const float*)d_in[0];
    const float* nsx  = (const float*)d_in[1];
    const float* nsy  = (const float*)d_in[2];
    const float* umap = (const float*)d_in[3];
    const int*   pw   = (const int*)d_in[4];
    float*       out  = (float*)d_out;

    int n = in_sizes[1];  // node_size_x has N elements
    int threads = 256;
    int elems_per_block = threads * 4;
    int blocks = (n + elems_per_block - 1) / elems_per_block;
    node_area_kernel_v5<<<blocks, threads>>>(pos, nsx, nsy, umap, pw, out, n);
}

// round 4
// speedup vs baseline: 1.3417x; 1.2881x over previous
#include <cuda_runtime.h>
#include <cuda_bf16.h>
#include <math.h>

// Problem constants (match reference)
#define NBX     512
#define NBY     512
#define BSX     1.953125f   // 1000/512, exact in fp32
#define BSY     1.953125f
#define INV_UPC 10.0f       // 1 / UNIT_PIN_CAP

// Quad map scratch: Q[bx][by] = {u[bx][by], u[bx][by1], u[bx1][by], u[bx1][by1]}
// with bx1 = min(bx+1, 511), by1 = min(by+1, 511). 4 MB static device array.
__device__ float4 g_quad[NBX * NBY];

__global__ __launch_bounds__(256) void build_quad_kernel(
    const float* __restrict__ umap)
{
    int idx = blockIdx.x * blockDim.x + threadIdx.x;
    if (idx >= NBX * NBY) return;
    int bx = idx >> 9;
    int by = idx & (NBY - 1);
    int bx1 = min(bx + 1, NBX - 1);
    int by1 = min(by + 1, NBY - 1);
    const float* r0 = umap + bx  * NBY;
    const float* r1 = umap + bx1 * NBY;
    float4 q;
    q.x = __ldg(&r0[by]);
    q.y = __ldg(&r0[by1]);
    q.z = __ldg(&r1[by]);
    q.w = __ldg(&r1[by1]);
    g_quad[idx] = q;
}

// Main kernel: 4 nodes per thread, ONE float4 gather per node.
__global__ __launch_bounds__(256) void node_area_kernel_v6(
    const float* __restrict__ pos,        // [2N]: x then y
    const float* __restrict__ nsx,        // [N]
    const float* __restrict__ nsy,        // [N]
    const int*   __restrict__ pw,         // [N]
    float*       __restrict__ out,        // [N]
    int n)
{
    int base = (blockIdx.x * blockDim.x + threadIdx.x) * 4;
    if (base >= n) return;
    // N is a multiple of 4, so full float4 accesses are always valid.

    float4 x4 = *(const float4*)(pos + base);
    float4 y4 = *(const float4*)(pos + n + base);
    float4 w4 = *(const float4*)(nsx + base);
    float4 h4 = *(const float4*)(nsy + base);
    int4   p4 = *(const int4*)(pw + base);

    float xs[4] = {x4.x, x4.y, x4.z, x4.w};
    float ys[4] = {y4.x, y4.y, y4.z, y4.w};
    float ws[4] = {w4.x, w4.y, w4.z, w4.w};
    float hs[4] = {h4.x, h4.y, h4.z, h4.w};
    int   ps[4] = {p4.x, p4.y, p4.z, p4.w};

    float res[4];

    #pragma unroll
    for (int k = 0; k < 4; k++) {
        float x = xs[k], y = ys[k];
        float hix = x + ws[k];
        float hiy = y + hs[k];

        // floor bin indices — fp32 division matches JAX edge behavior
        int bx0 = (int)floorf(x / BSX);
        int by0 = (int)floorf(y / BSY);

        // Overlaps use UNCLIPPED bin positions (as in reference)
        float blx0 = (float)bx0 * BSX;
        float ox0 = fmaxf(fminf(hix, blx0 + BSX)        - fmaxf(x, blx0),       0.0f);
        float ox1 = fmaxf(fminf(hix, blx0 + 2.0f * BSX) - fmaxf(x, blx0 + BSX), 0.0f);

        float bly0 = (float)by0 * BSY;
        float oy0 = fmaxf(fminf(hiy, bly0 + BSY)        - fmaxf(y, bly0),       0.0f);
        float oy1 = fmaxf(fminf(hiy, bly0 + 2.0f * BSY) - fmaxf(y, bly0 + BSY), 0.0f);

        // Clipped base indices (x,y >= 0 so only upper clip can matter;
        // the +1 clip is baked into the quad map)
        int bx0c = min(max(bx0, 0), NBX - 1);
        int by0c = min(max(by0, 0), NBY - 1);

        float4 u = __ldg(&g_quad[(bx0c << 9) | by0c]);

        float area = ox0 * (oy0 * u.x + oy1 * u.y)
                   + ox1 * (oy0 * u.z + oy1 * u.w);

        res[k] = area * (float)ps[k] * INV_UPC / (ws[k] * hs[k]);
    }

    float4 r;
    r.x = res[0]; r.y = res[1]; r.z = res[2]; r.w = res[3];
    *(float4*)(out + base) = r;
}

extern "C" void kernel_launch(void* const* d_in, const int* in_sizes, int n_in,
                              void* d_out, int out_size)
{
    const float* pos  = (const float*)d_in[0];
    const float* nsx  = (const float*)d_in[1];
    const float* nsy  = (const float*)d_in[2];
    const float* umap = (const float*)d_in[3];
    const int*   pw   = (const int*)d_in[4];
    float*       out  = (float*)d_out;

    int n = in_sizes[1];  // node_size_x has N elements

    // Pass 1: build the quad map (clip-at-edge baked in)
    {
        int total = NBX * NBY;
        int threads = 256;
        int blocks = (total + threads - 1) / threads;
        build_quad_kernel<<<blocks, threads>>>(umap);
    }

    // Pass 2: per-node area with a single float4 gather each
    {
        int threads = 256;
        int elems_per_block = threads * 4;
        int blocks = (n + elems_per_block - 1) / elems_per_block;
        node_area_kernel_v6<<<blocks, threads>>>(pos, nsx, nsy, pw, out, n);
    }
}

// round 5
// speedup vs baseline: 1.3882x; 1.0347x over previous
#include <cuda_runtime.h>
#include <cuda_bf16.h>
#include <math.h>

// Problem constants (match reference)
#define NBX     512
#define NBY     512
#define BSX     1.953125f   // 1000/512, exact in fp32
#define BSY     1.953125f
#define INV_UPC 10.0f       // 1 / UNIT_PIN_CAP

// Quad map scratch: Q[bx][by] = {u[bx][by], u[bx][by1], u[bx1][by], u[bx1][by1]}
// with bx1 = min(bx+1, 511), by1 = min(by+1, 511). 4 MB static device array.
__device__ float4 g_quad[NBX * NBY];

__global__ __launch_bounds__(256) void build_quad_kernel(
    const float* __restrict__ umap)
{
    int idx = blockIdx.x * blockDim.x + threadIdx.x;
    if (idx >= NBX * NBY) return;
    int bx = idx >> 9;
    int by = idx & (NBY - 1);
    int bx1 = min(bx + 1, NBX - 1);
    int by1 = min(by + 1, NBY - 1);
    const float* r0 = umap + bx  * NBY;
    const float* r1 = umap + bx1 * NBY;
    float4 q;
    q.x = __ldg(&r0[by]);
    q.y = __ldg(&r0[by1]);
    q.z = __ldg(&r1[by]);
    q.w = __ldg(&r1[by1]);
    g_quad[idx] = q;
}

__device__ __forceinline__ float node_area(
    float x, float y, float w, float h, int p)
{
    float hix = x + w;
    float hiy = y + h;

    // floor bin indices — fp32 division matches JAX edge behavior
    int bx0 = (int)floorf(x / BSX);
    int by0 = (int)floorf(y / BSY);

    // Overlaps use UNCLIPPED bin positions (as in reference)
    float blx0 = (float)bx0 * BSX;
    float ox0 = fmaxf(fminf(hix, blx0 + BSX)        - fmaxf(x, blx0),       0.0f);
    float ox1 = fmaxf(fminf(hix, blx0 + 2.0f * BSX) - fmaxf(x, blx0 + BSX), 0.0f);

    float bly0 = (float)by0 * BSY;
    float oy0 = fmaxf(fminf(hiy, bly0 + BSY)        - fmaxf(y, bly0),       0.0f);
    float oy1 = fmaxf(fminf(hiy, bly0 + 2.0f * BSY) - fmaxf(y, bly0 + BSY), 0.0f);

    // Clipped base indices; +1 clip is baked into the quad map
    int bx0c = min(max(bx0, 0), NBX - 1);
    int by0c = min(max(by0, 0), NBY - 1);

    float4 u = __ldg(&g_quad[(bx0c << 9) | by0c]);

    float area = ox0 * (oy0 * u.x + oy1 * u.y)
               + ox1 * (oy0 * u.z + oy1 * u.w);

    return area * (float)p * INV_UPC / (w * h);
}

// 2 nodes per thread: low register count -> 8 blocks/SM -> 64 warps resident.
__global__ __launch_bounds__(256, 8) void node_area_kernel_v7(
    const float* __restrict__ pos,        // [2N]: x then y
    const float* __restrict__ nsx,        // [N]
    const float* __restrict__ nsy,        // [N]
    const int*   __restrict__ pw,         // [N]
    float*       __restrict__ out,        // [N]
    int n)
{
    int base = (blockIdx.x * blockDim.x + threadIdx.x) * 2;
    if (base >= n) return;
    // N is a multiple of 2, so full float2 accesses are always valid.

    float2 x2 = *(const float2*)(pos + base);
    float2 y2 = *(const float2*)(pos + n + base);
    float2 w2 = *(const float2*)(nsx + base);
    float2 h2 = *(const float2*)(nsy + base);
    int2   p2 = *(const int2*)(pw + base);

    float2 r;
    r.x = node_area(x2.x, y2.x, w2.x, h2.x, p2.x);
    r.y = node_area(x2.y, y2.y, w2.y, h2.y, p2.y);
    *(float2*)(out + base) = r;
}

extern "C" void kernel_launch(void* const* d_in, const int* in_sizes, int n_in,
                              void* d_out, int out_size)
{
    const float* pos  = (const float*)d_in[0];
    const float* nsx  = (const float*)d_in[1];
    const float* nsy  = (const float*)d_in[2];
    const float* umap = (const float*)d_in[3];
    const int*   pw   = (const int*)d_in[4];
    float*       out  = (float*)d_out;

    int n = in_sizes[1];  // node_size_x has N elements

    // Pass 1: build the quad map (clip-at-edge baked in)
    {
        int total = NBX * NBY;
        int threads = 256;
        int blocks = (total + threads - 1) / threads;
        build_quad_kernel<<<blocks, threads>>>(umap);
    }

    // Pass 2: per-node area with a single float4 gather each
    {
        int threads = 256;
        int elems_per_block = threads * 2;
        int blocks = (n + elems_per_block - 1) / elems_per_block;
        node_area_kernel_v7<<<blocks, threads>>>(pos, nsx, nsy, pw, out, n);
    }
}

// round 6
// speedup vs baseline: 1.5085x; 1.0866x over previous
#include <cuda_runtime.h>
#include <cuda_bf16.h>
#include <math.h>

// Problem constants (match reference)
#define NBX     512
#define NBY     512
#define BSX     1.953125f   // 1000/512, exact in fp32
#define BSY     1.953125f
#define INV_BS  0.512f      // rn(1/BSX); product path, exact-div fallback near bins
#define INV_UPC 10.0f       // 1 / UNIT_PIN_CAP

// Quad map scratch: Q[bx][by] = {u[bx][by], u[bx][by1], u[bx1][by], u[bx1][by1]}
// with bx1 = min(bx+1, 511), by1 = min(by+1, 511). 4 MB static device array.
__device__ float4 g_quad[NBX * NBY];

__global__ __launch_bounds__(256) void build_quad_kernel(
    const float* __restrict__ umap)
{
    int idx = blockIdx.x * blockDim.x + threadIdx.x;
    if (idx >= NBX * NBY) return;
    int bx = idx >> 9;
    int by = idx & (NBY - 1);
    int bx1 = min(bx + 1, NBX - 1);
    int by1 = min(by + 1, NBY - 1);
    const float* r0 = umap + bx  * NBY;
    const float* r1 = umap + bx1 * NBY;
    float4 q;
    q.x = __ldg(&r0[by]);
    q.y = __ldg(&r0[by1]);
    q.z = __ldg(&r1[by]);
    q.w = __ldg(&r1[by1]);
    g_quad[idx] = q;
}

__device__ __forceinline__ float node_area(
    float x, float y, float w, float h, float ps)
{
    // Fast bin quotients via multiply; both error bounds < 2.5e-7 relative.
    float qx = x * INV_BS;
    float qy = y * INV_BS;

    // If either quotient is within ~4 ulp of an integer, the fast floor could
    // disagree with the reference's floor(div.rn(x/BSX)). Redo exactly.
    float dx = fabsf(qx - rintf(qx));
    float dy = fabsf(qy - rintf(qy));
    float tx = fmaxf(qx, 1.0f) * 5e-7f;
    float ty = fmaxf(qy, 1.0f) * 5e-7f;
    if (dx < tx || dy < ty) {            // rare (~1e-4 of nodes)
        qx = x / BSX;
        qy = y / BSY;
    }

    float fbx = floorf(qx);
    float fby = floorf(qy);

    float hix = x + w;
    float hiy = y + h;

    // Overlaps use UNCLIPPED bin positions (as in reference).
    // fbx*BSX is exact for integer fbx in [0,512].
    float blx0 = fbx * BSX;
    float ox0 = fmaxf(fminf(hix, blx0 + BSX)        - fmaxf(x, blx0),       0.0f);
    float ox1 = fmaxf(fminf(hix, blx0 + 2.0f * BSX) - fmaxf(x, blx0 + BSX), 0.0f);

    float bly0 = fby * BSY;
    float oy0 = fmaxf(fminf(hiy, bly0 + BSY)        - fmaxf(y, bly0),       0.0f);
    float oy1 = fmaxf(fminf(hiy, bly0 + 2.0f * BSY) - fmaxf(y, bly0 + BSY), 0.0f);

    // Clipped base indices; the +1 clip is baked into the quad map.
    int bx0c = min(max((int)fbx, 0), NBX - 1);
    int by0c = min(max((int)fby, 0), NBY - 1);

    float4 u = __ldg(&g_quad[(bx0c << 9) | by0c]);

    float area = ox0 * (oy0 * u.x + oy1 * u.y)
               + ox1 * (oy0 * u.z + oy1 * u.w);

    // Fast division: ~2 ulp, well inside the 1e-3 budget.
    return __fdividef(area * ps, w * h);
}

// 2 nodes per thread: low register count -> 8 blocks/SM -> 64 warps resident.
__global__ __launch_bounds__(256, 8) void node_area_kernel_v8(
    const float* __restrict__ pos,        // [2N]: x then y
    const float* __restrict__ nsx,        // [N]
    const float* __restrict__ nsy,        // [N]
    const int*   __restrict__ pw,         // [N]
    float*       __restrict__ out,        // [N]
    int n)
{
    int base = (blockIdx.x * blockDim.x + threadIdx.x) * 2;
    if (base >= n) return;
    // N is a multiple of 2, so full float2 accesses are always valid.

    float2 x2 = *(const float2*)(pos + base);
    float2 y2 = *(const float2*)(pos + n + base);
    float2 w2 = *(const float2*)(nsx + base);
    float2 h2 = *(const float2*)(nsy + base);
    int2   p2 = *(const int2*)(pw + base);

    float2 r;
    r.x = node_area(x2.x, y2.x, w2.x, h2.x, (float)p2.x * INV_UPC);
    r.y = node_area(x2.y, y2.y, w2.y, h2.y, (float)p2.y * INV_UPC);
    *(float2*)(out + base) = r;
}

extern "C" void kernel_launch(void* const* d_in, const int* in_sizes, int n_in,
                              void* d_out, int out_size)
{
    const float* pos  = (const float*)d_in[0];
    const float* nsx  = (const float*)d_in[1];
    const float* nsy  = (const float*)d_in[2];
    const float* umap = (const float*)d_in[3];
    const int*   pw   = (const int*)d_in[4];
    float*       out  = (float*)d_out;

    int n = in_sizes[1];  // node_size_x has N elements

    // Pass 1: build the quad map (clip-at-edge baked in)
    {
        int total = NBX * NBY;
        int threads = 256;
        int blocks = (total + threads - 1) / threads;
        build_quad_kernel<<<blocks, threads>>>(umap);
    }

    // Pass 2: per-node area with a single float4 gather each
    {
        int threads = 256;
        int elems_per_block = threads * 2;
        int blocks = (n + elems_per_block - 1) / elems_per_block;
        node_area_kernel_v8<<<blocks, threads>>>(pos, nsx, nsy, pw, out, n);
    }
}